// round 11
// baseline (speedup 1.0000x reference)
#include <cuda_runtime.h>
#include <cmath>
#include <stdint.h>

#define AMAX 1024
#define WORDS 32
#define BMAX 2
#define CMAX 80
#define NK 8           // compact neighbor-list capacity (per box)
#define RPB 13         // ceil(1024/80) adjacency rows per block

// Scratch (static device arrays; no dynamic allocation allowed)
__device__ unsigned g_adjT[BMAX * WORDS * AMAX];          // 256 KB (fallback, degree>NK only)
__device__ unsigned short g_nbr[BMAX * AMAX * NK];        // 32 KB compact neighbor lists
__device__ volatile unsigned g_ntag[BMAX * AMAX];         // per-row ready tag: (epoch<<12)|degree
__device__ unsigned g_blkctr[BMAX * CMAX];                // per-block epoch (single writer)

__device__ __forceinline__ float4 regress_box(const float* __restrict__ reg,
                                              const float4* __restrict__ anchors4,
                                              int b, int t, int A, float Wf, float Hf) {
    float4 av = anchors4[t];                       // one LDG.128
    float w = av.z - av.x, h = av.w - av.y;
    float cx = av.x + 0.5f * w, cy = av.y + 0.5f * h;
    const float* rb = reg + (size_t)b * 4 * A;
    float dx = rb[0 * A + t] * 0.1f;
    float dy = rb[1 * A + t] * 0.1f;
    float dw = rb[2 * A + t] * 0.2f;
    float dh = rb[3 * A + t] * 0.2f;
    float pcx = cx + dx * w, pcy = cy + dy * h;
    float pw = expf(dw) * w, ph = expf(dh) * h;
    float4 r;
    r.x = fmaxf(pcx - 0.5f * pw, 0.0f);
    r.y = fmaxf(pcy - 0.5f * ph, 0.0f);
    r.z = fminf(pcx + 0.5f * pw, Wf);
    r.w = fminf(pcy + 0.5f * ph, Hf);
    return r;
}

// One fused kernel, NO global barrier: per-row readiness tags.
// Grid = B*C blocks x 1024 threads, one (b,c) each.
// Phase 1a: warp w owns column-word w; 13 rows. Phase 1b: 13 warps emit rows
// with epoch-tagged publish. Phase 2 (all warps; 19 warps start immediately):
// poll OWN row tag only, then async monotone-dataflow NMS + fused output.
__global__ void __launch_bounds__(1024, 2) fused_kernel(
    const float* __restrict__ cls, const float* __restrict__ reg,
    const float* __restrict__ anchors, float* __restrict__ out,
    int A, int C, int nBlocks, float Wf, float Hf) {
    __shared__ float4 sbox[AMAX];                   // 16 KB
    __shared__ float ssc[AMAX];                     // 4 KB
    __shared__ float sarea[AMAX];                   // 4 KB box areas
    __shared__ unsigned sadj[RPB * 32];             // 1.7 KB ballot tile [row][word]
    __shared__ volatile unsigned char sstate[AMAX]; // 0=undec, 1=dropped, 2=kept
    __shared__ unsigned sepoch;                     // this launch's tag epoch
    int bid = blockIdx.x;
    int i = threadIdx.x;
    int lane = i & 31, wid = i >> 5;
    int b = bid / C;
    int c = bid - b * C;
    int base = c * RPB;                             // first assigned row

    // Stage: epoch fetch + regress own batch boxes + areas + scores.
    if (i == 0) {
        unsigned e = g_blkctr[bid] + 1;             // single writer per slot;
        g_blkctr[bid] = e;                          // launches serialize -> safe
        sepoch = e & 0xFFFFFu;
    }
    float s = cls[(size_t)bid * AMAX + i];
    float4 mybx = regress_box(reg, (const float4*)anchors, b, i, A, Wf, Hf);
    sbox[i] = mybx;
    sarea[i] = (mybx.z - mybx.x) * (mybx.w - mybx.y);  // same expr: bit-identical
    ssc[i] = s;
    sstate[i] = 0;
    __syncthreads();
    unsigned epoch = sepoch;

    // ---- Phase 1a: warp wid = column-word wid; 2 rows per iteration ----
    {
        float4 bj = sbox[wid * 32 + lane];          // loop-invariant column box
        float ajj = sarea[wid * 32 + lane];
        #pragma unroll
        for (int k = 0; k + 1 < RPB; k += 2) {
            int r0 = base + k;
            if (r0 >= AMAX) break;
            bool h1 = (r0 + 1 < AMAX);
            float4 b0 = sbox[r0];
            float4 b1 = h1 ? sbox[r0 + 1] : b0;
            float a0 = sarea[r0];
            float a1 = h1 ? sarea[r0 + 1] : a0;
            float i0 = fmaxf(fminf(b0.z, bj.z) - fmaxf(b0.x, bj.x), 0.0f) *
                       fmaxf(fminf(b0.w, bj.w) - fmaxf(b0.y, bj.y), 0.0f);
            float i1 = fmaxf(fminf(b1.z, bj.z) - fmaxf(b1.x, bj.x), 0.0f) *
                       fmaxf(fminf(b1.w, bj.w) - fmaxf(b1.y, bj.y), 0.0f);
            // Conservative filter: IoU>0.5 => 3*inter > a+aj (real arithmetic);
            // 0.999 margin absorbs fp rounding. Exact decision via IEEE div
            // below -> bit-identical to reference.
            bool c0 = 3.0f * i0 >= 0.999f * (a0 + ajj);
            bool c1 = 3.0f * i1 >= 0.999f * (a1 + ajj);
            unsigned cb = __ballot_sync(0xffffffffu, c0 || c1);
            unsigned bal0 = 0, bal1 = 0;
            if (cb) {                                  // rare path (warp-uniform)
                bool adj0 = c0 && (__fdiv_rn(i0, fmaxf((a0 + ajj) - i0, 1e-9f)) > 0.5f);
                bool adj1 = c1 && (__fdiv_rn(i1, fmaxf((a1 + ajj) - i1, 1e-9f)) > 0.5f);
                bal0 = __ballot_sync(0xffffffffu, adj0);
                bal1 = __ballot_sync(0xffffffffu, adj1);
            }
            if (lane == 0) {
                sadj[k * 32 + wid] = bal0;
                if (h1) sadj[(k + 1) * 32 + wid] = bal1;
            }
        }
        {   // tail row (RPB odd)
            int r0 = base + RPB - 1;
            if (r0 < AMAX) {
                float4 b0 = sbox[r0];
                float a0 = sarea[r0];
                float i0 = fmaxf(fminf(b0.z, bj.z) - fmaxf(b0.x, bj.x), 0.0f) *
                           fmaxf(fminf(b0.w, bj.w) - fmaxf(b0.y, bj.y), 0.0f);
                bool c0 = 3.0f * i0 >= 0.999f * (a0 + ajj);
                unsigned cb = __ballot_sync(0xffffffffu, c0);
                unsigned bal0 = 0;
                if (cb) {
                    bool adj0 = c0 && (__fdiv_rn(i0, fmaxf((a0 + ajj) - i0, 1e-9f)) > 0.5f);
                    bal0 = __ballot_sync(0xffffffffu, adj0);
                }
                if (lane == 0) sadj[(RPB - 1) * 32 + wid] = bal0;
            }
        }
    }
    __syncthreads();   // sadj complete (only 1b reads it; cheap, keeps 1a/1b clean)

    // ---- Phase 1b: warps 0..RPB-1 emit + publish row (base+wid) ----
    if (wid < RPB && base + wid < AMAX) {
        int row = base + wid;
        unsigned m = sadj[wid * 32 + lane];
        if (lane == (row >> 5)) m &= ~(1u << (row & 31));    // drop self bit

        int cnt = __popc(m);
        int scan = cnt;
        #pragma unroll
        for (int d = 1; d < 32; d <<= 1) {
            int t = __shfl_up_sync(0xffffffffu, scan, d);
            if (lane >= d) scan += t;
        }
        int excl = scan - cnt;
        int tot = __shfl_sync(0xffffffffu, scan, 31);
        unsigned short* np = g_nbr + ((size_t)b * AMAX + row) * NK;
        unsigned mm = m;
        int pos = excl;
        while (mm && pos < NK) {
            int t2 = __ffs(mm) - 1; mm &= mm - 1;
            np[pos++] = (unsigned short)(lane * 32 + t2);
        }
        if (tot > NK)                                      // fallback rows only
            g_adjT[((size_t)b * WORDS + lane) * AMAX + row] = m;
        __threadfence();             // release this lane's list/fallback stores
        __syncwarp();                // all lanes' fences done before publish
        if (lane == 0)
            g_ntag[b * AMAX + row] = (epoch << 12) | (unsigned)tot;  // publish
    }
    // NO block/global barrier: warps proceed to phase 2 independently.

    // ---------------- Phase 2: per-row readiness + async dataflow NMS ----------------
    unsigned tag;
    {
        volatile unsigned* tp = &g_ntag[b * AMAX + i];
        while (((tag = *tp) >> 12) != epoch) __nanosleep(64);  // own row only
    }
    __threadfence();                  // acquire: list visible after tag match
    int total = (int)(tag & 0xFFFu);
    uint4 nv = *(const uint4*)&g_nbr[((size_t)b * AMAX + i) * NK];
    bool ovf = total > NK;            // rare high-degree fallback
    int cnt = ovf ? 0 : total;

    // Higher-ranked neighbors (score desc, index asc) into registers.
    unsigned short js[NK];
    int nh = 0;
    {
        unsigned words[4] = {nv.x, nv.y, nv.z, nv.w};
        #pragma unroll
        for (int k = 0; k < NK; ++k) {
            if (k < cnt) {
                int j = (words[k >> 1] >> ((k & 1) * 16)) & 0xFFFF;
                float sj = ssc[j];
                if (sj > s || (sj == s && j < i)) js[nh++] = (unsigned short)j;
            }
        }
    }

    bool valid = s > 0.05f;
    if (!valid) {
        sstate[i] = 1;                // never kept, never suppresses
    } else if (!ovf && nh == 0) {
        sstate[i] = 2;                // top of its chain: kept
    } else {
        // Spin until all higher neighbors decided or one of them kept.
        // Monotone byte per box (0 -> 1|2): one volatile LDS per hop.
        // Unready neighbors just read as 0 (undecided) -> safe overlap with
        // phase 1 of other blocks; eventually all rows publish -> progress.
        const unsigned* adjT = g_adjT + (size_t)b * WORDS * AMAX;
        for (;;) {
            bool sup = false, alld = true;
            if (!ovf) {
                for (int k = 0; k < nh; ++k) {
                    unsigned char v = sstate[js[k]];
                    if (v == 2) { sup = true; break; }
                    if (v == 0) alld = false;
                }
            } else {
                #pragma unroll
                for (int w = 0; w < WORDS; ++w) {
                    unsigned mm = adjT[w * AMAX + i];
                    while (mm) {
                        int bit = __ffs(mm) - 1; mm &= mm - 1;
                        int j = w * 32 + bit;
                        float sj = ssc[j];
                        if (sj > s || (sj == s && j < i)) {
                            unsigned char v = sstate[j];
                            if (v == 2) { sup = true; }
                            else if (v == 0) alld = false;
                        }
                    }
                    if (sup) break;
                }
            }
            if (sup)  { sstate[i] = 1; break; }
            if (alld) { sstate[i] = 2; break; }
        }
    }
    __syncthreads();                  // all decided; sstate stable

    // Coalesced float4 output: 5120 floats/block = 1280 float4.
    const float* sboxf = (const float*)sbox;
    float4* obase4 = (float4*)(out + (size_t)bid * AMAX * 5);
    #pragma unroll
    for (int r = 0; r < 2; ++r) {
        int t = r * 1024 + i;
        if (t < (AMAX * 5) / 4) {
            float4 v;
            float* vf = (float*)&v;
            #pragma unroll
            for (int k = 0; k < 4; ++k) {
                int idx = t * 4 + k;
                int a = idx / 5;
                int f = idx - a * 5;
                float x = 0.0f;
                if (sstate[a] == 2) x = (f == 0) ? ssc[a] : sboxf[a * 4 + (f - 1)];
                vf[k] = x;
            }
            obase4[t] = v;
        }
    }
}

extern "C" void kernel_launch(void* const* d_in, const int* in_sizes, int n_in,
                              void* d_out, int out_size) {
    // metadata order: image, cls_pred, reg_pred, anchors
    const float* cls = (const float*)d_in[1];
    const float* reg = (const float*)d_in[2];
    const float* anchors = (const float*)d_in[3];

    int A = in_sizes[3] / 4;                 // 1024
    int B = in_sizes[2] / (4 * A);           // 2
    int C = in_sizes[1] / (B * A);           // 80
    long long hw = (long long)in_sizes[0] / (3LL * B);
    int H = (int)(sqrt((double)hw) + 0.5);   // 2048 (image used for shape only)
    float Hf = (float)H, Wf = (float)H;

    int nBlocks = B * C;                     // 160 blocks, all co-resident (2/SM)
    fused_kernel<<<nBlocks, 1024>>>(cls, reg, anchors, (float*)d_out,
                                    A, C, nBlocks, Wf, Hf);
}

// round 12
// speedup vs baseline: 1.0821x; 1.0821x over previous
#include <cuda_runtime.h>
#include <cmath>
#include <stdint.h>

#define AMAX 1024
#define WORDS 32
#define BMAX 2
#define CMAX 80
#define NK 8           // compact neighbor-list capacity (per box)
#define RPB 13         // ceil(1024/80) rows per block

// Scratch (static device arrays; no dynamic allocation allowed)
__device__ float4 g_boxes[BMAX * AMAX];                   // 32 KB regressed boxes
__device__ unsigned g_adjT[BMAX * WORDS * AMAX];          // 256 KB (fallback, degree>NK only)
__device__ unsigned short g_nbr[BMAX * AMAX * NK];        // 32 KB compact neighbor lists
__device__ int g_ncnt[BMAX * AMAX];                       // 8 KB degrees
__device__ int g_bdone[BMAX];                             // epoch counter: boxes ready
__device__ int g_adone[BMAX];                             // epoch counter: adjacency ready

__device__ __forceinline__ float4 regress_box(const float* __restrict__ reg,
                                              const float4* __restrict__ anchors4,
                                              int b, int t, int A, float Wf, float Hf) {
    float4 av = anchors4[t];                       // one LDG.128
    float w = av.z - av.x, h = av.w - av.y;
    float cx = av.x + 0.5f * w, cy = av.y + 0.5f * h;
    const float* rb = reg + (size_t)b * 4 * A;
    float dx = rb[0 * A + t] * 0.1f;
    float dy = rb[1 * A + t] * 0.1f;
    float dw = rb[2 * A + t] * 0.2f;
    float dh = rb[3 * A + t] * 0.2f;
    float pcx = cx + dx * w, pcy = cy + dy * h;
    float pw = expf(dw) * w, ph = expf(dh) * h;
    float4 r;
    r.x = fmaxf(pcx - 0.5f * pw, 0.0f);
    r.y = fmaxf(pcy - 0.5f * ph, 0.0f);
    r.z = fminf(pcx + 0.5f * pw, Wf);
    r.w = fminf(pcy + 0.5f * ph, Hf);
    return r;
}

// Epoch wait: each counter gets exactly C increments per launch (launches
// serialize on the stream), so target = v - v%C + C is launch-consistent.
// Monotone counters -> replay-safe with no reset.
__device__ __forceinline__ void signal_and_wait(int* ctr, int C) {
    __threadfence();                           // release this block's stores
    int v = atomicAdd(ctr, 1);
    int target = v - (v % C) + C;
    volatile int* dp = ctr;
    while (*dp < target) __nanosleep(64);
    __threadfence();                           // acquire
}

// One fused kernel. Grid = B*C blocks x 1024 threads, one (b,c) each.
// Phase 0: regress ONLY this block's 13 rows (kills 80x-duplicated expf/MUFU),
// publish to g_boxes, epoch-wait, bulk-load all 1024 batch boxes (1 LDG.128/thr).
// Phase 1: adjacency rows (warp-per-column-word), publish, epoch-wait.
// Phase 2: async monotone-dataflow NMS + fused coalesced float4 output.
__global__ void __launch_bounds__(1024, 2) fused_kernel(
    const float* __restrict__ cls, const float* __restrict__ reg,
    const float* __restrict__ anchors, float* __restrict__ out,
    int A, int C, int nBlocks, float Wf, float Hf) {
    __shared__ float4 sbox[AMAX];                   // 16 KB
    __shared__ float ssc[AMAX];                     // 4 KB
    __shared__ float sarea[AMAX];                   // 4 KB box areas
    __shared__ unsigned sadj[RPB * 32];             // 1.7 KB ballot tile [row][word]
    __shared__ volatile unsigned char sstate[AMAX]; // 0=undec, 1=dropped, 2=kept
    int bid = blockIdx.x;
    int i = threadIdx.x;
    int lane = i & 31, wid = i >> 5;
    int b = bid / C;
    int c = bid - b * C;
    int base = c * RPB;                             // first assigned row

    // ---- Phase 0: stage scores; regress ONLY own 13 rows; publish boxes ----
    float s = cls[(size_t)bid * AMAX + i];
    ssc[i] = s;
    sstate[i] = 0;
    if (i < RPB && base + i < AMAX) {               // 13 threads, ~26 MUFU total
        float4 bx = regress_box(reg, (const float4*)anchors, b, base + i, A, Wf, Hf);
        g_boxes[b * AMAX + base + i] = bx;          // bit-identical values as before
    }
    __syncthreads();
    if (i == 0) signal_and_wait(&g_bdone[b], C);
    __syncthreads();                                // all batch boxes published

    // Bulk-load all 1024 boxes: one coalesced LDG.128 per thread.
    float4 mybx = g_boxes[b * AMAX + i];
    sbox[i] = mybx;
    sarea[i] = (mybx.z - mybx.x) * (mybx.w - mybx.y);  // same expr: bit-identical
    __syncthreads();

    // ---- Phase 1a: warp wid = column-word wid; 2 rows per iteration ----
    {
        float4 bj = sbox[wid * 32 + lane];          // loop-invariant column box
        float ajj = sarea[wid * 32 + lane];
        #pragma unroll
        for (int k = 0; k + 1 < RPB; k += 2) {
            int r0 = base + k;
            if (r0 >= AMAX) break;
            bool h1 = (r0 + 1 < AMAX);
            float4 b0 = sbox[r0];
            float4 b1 = h1 ? sbox[r0 + 1] : b0;
            float a0 = sarea[r0];
            float a1 = h1 ? sarea[r0 + 1] : a0;
            float i0 = fmaxf(fminf(b0.z, bj.z) - fmaxf(b0.x, bj.x), 0.0f) *
                       fmaxf(fminf(b0.w, bj.w) - fmaxf(b0.y, bj.y), 0.0f);
            float i1 = fmaxf(fminf(b1.z, bj.z) - fmaxf(b1.x, bj.x), 0.0f) *
                       fmaxf(fminf(b1.w, bj.w) - fmaxf(b1.y, bj.y), 0.0f);
            // Conservative filter: IoU>0.5 => 3*inter > a+aj (real arithmetic);
            // 0.999 margin absorbs fp rounding. Exact decision via IEEE div
            // below -> bit-identical to reference.
            bool c0 = 3.0f * i0 >= 0.999f * (a0 + ajj);
            bool c1 = 3.0f * i1 >= 0.999f * (a1 + ajj);
            unsigned cb = __ballot_sync(0xffffffffu, c0 || c1);
            unsigned bal0 = 0, bal1 = 0;
            if (cb) {                                  // rare path (warp-uniform)
                bool adj0 = c0 && (__fdiv_rn(i0, fmaxf((a0 + ajj) - i0, 1e-9f)) > 0.5f);
                bool adj1 = c1 && (__fdiv_rn(i1, fmaxf((a1 + ajj) - i1, 1e-9f)) > 0.5f);
                bal0 = __ballot_sync(0xffffffffu, adj0);
                bal1 = __ballot_sync(0xffffffffu, adj1);
            }
            if (lane == 0) {
                sadj[k * 32 + wid] = bal0;
                if (h1) sadj[(k + 1) * 32 + wid] = bal1;
            }
        }
        {   // tail row (RPB odd)
            int r0 = base + RPB - 1;
            if (r0 < AMAX) {
                float4 b0 = sbox[r0];
                float a0 = sarea[r0];
                float i0 = fmaxf(fminf(b0.z, bj.z) - fmaxf(b0.x, bj.x), 0.0f) *
                           fmaxf(fminf(b0.w, bj.w) - fmaxf(b0.y, bj.y), 0.0f);
                bool c0 = 3.0f * i0 >= 0.999f * (a0 + ajj);
                unsigned cb = __ballot_sync(0xffffffffu, c0);
                unsigned bal0 = 0;
                if (cb) {
                    bool adj0 = c0 && (__fdiv_rn(i0, fmaxf((a0 + ajj) - i0, 1e-9f)) > 0.5f);
                    bal0 = __ballot_sync(0xffffffffu, adj0);
                }
                if (lane == 0) sadj[(RPB - 1) * 32 + wid] = bal0;
            }
        }
    }
    __syncthreads();

    // ---- Phase 1b: warps 0..RPB-1 emit row (base+wid): lists + rare fallback ----
    if (wid < RPB && base + wid < AMAX) {
        int row = base + wid;
        unsigned m = sadj[wid * 32 + lane];
        if (lane == (row >> 5)) m &= ~(1u << (row & 31));    // drop self bit

        int cnt = __popc(m);
        int scan = cnt;
        #pragma unroll
        for (int d = 1; d < 32; d <<= 1) {
            int t = __shfl_up_sync(0xffffffffu, scan, d);
            if (lane >= d) scan += t;
        }
        int excl = scan - cnt;
        int tot = __shfl_sync(0xffffffffu, scan, 31);
        unsigned short* np = g_nbr + ((size_t)b * AMAX + row) * NK;
        unsigned mm = m;
        int pos = excl;
        while (mm && pos < NK) {
            int t2 = __ffs(mm) - 1; mm &= mm - 1;
            np[pos++] = (unsigned short)(lane * 32 + t2);
        }
        if (lane == 0) g_ncnt[b * AMAX + row] = tot;
        if (tot > NK)                                      // fallback rows only
            g_adjT[((size_t)b * WORDS + lane) * AMAX + row] = m;
    }
    __syncthreads();                  // all this block's rows written (CTA HB)
    if (i == 0) signal_and_wait(&g_adone[b], C);
    __syncthreads();                  // adjacency for batch b visible to block

    // ---------------- Phase 2: async monotone-dataflow NMS ----------------
    int total = g_ncnt[b * AMAX + i];
    uint4 nv = *(const uint4*)&g_nbr[((size_t)b * AMAX + i) * NK];
    bool ovf = total > NK;            // rare high-degree fallback
    int cnt = ovf ? 0 : total;

    // Higher-ranked neighbors (score desc, index asc) into registers.
    unsigned short js[NK];
    int nh = 0;
    {
        unsigned words[4] = {nv.x, nv.y, nv.z, nv.w};
        #pragma unroll
        for (int k = 0; k < NK; ++k) {
            if (k < cnt) {
                int j = (words[k >> 1] >> ((k & 1) * 16)) & 0xFFFF;
                float sj = ssc[j];
                if (sj > s || (sj == s && j < i)) js[nh++] = (unsigned short)j;
            }
        }
    }

    bool valid = s > 0.05f;
    if (!valid) {
        sstate[i] = 1;                // never kept, never suppresses
    } else if (!ovf && nh == 0) {
        sstate[i] = 2;                // top of its chain: kept
    } else {
        // Spin until all higher neighbors decided or one of them kept.
        // Monotone byte per box (0 -> 1|2): one volatile LDS per hop, no fences.
        // Min-rank undecided box always has all higher nbrs decided -> progress.
        const unsigned* adjT = g_adjT + (size_t)b * WORDS * AMAX;
        for (;;) {
            bool sup = false, alld = true;
            if (!ovf) {
                for (int k = 0; k < nh; ++k) {
                    unsigned char v = sstate[js[k]];
                    if (v == 2) { sup = true; break; }
                    if (v == 0) alld = false;
                }
            } else {
                #pragma unroll
                for (int w = 0; w < WORDS; ++w) {
                    unsigned mm = adjT[w * AMAX + i];
                    while (mm) {
                        int bit = __ffs(mm) - 1; mm &= mm - 1;
                        int j = w * 32 + bit;
                        float sj = ssc[j];
                        if (sj > s || (sj == s && j < i)) {
                            unsigned char v = sstate[j];
                            if (v == 2) { sup = true; }
                            else if (v == 0) alld = false;
                        }
                    }
                    if (sup) break;
                }
            }
            if (sup)  { sstate[i] = 1; break; }
            if (alld) { sstate[i] = 2; break; }
        }
    }
    __syncthreads();                  // all decided; sstate stable

    // Coalesced float4 output: 5120 floats/block = 1280 float4.
    const float* sboxf = (const float*)sbox;
    float4* obase4 = (float4*)(out + (size_t)bid * AMAX * 5);
    #pragma unroll
    for (int r = 0; r < 2; ++r) {
        int t = r * 1024 + i;
        if (t < (AMAX * 5) / 4) {
            float4 v;
            float* vf = (float*)&v;
            #pragma unroll
            for (int k = 0; k < 4; ++k) {
                int idx = t * 4 + k;
                int a = idx / 5;
                int f = idx - a * 5;
                float x = 0.0f;
                if (sstate[a] == 2) x = (f == 0) ? ssc[a] : sboxf[a * 4 + (f - 1)];
                vf[k] = x;
            }
            obase4[t] = v;
        }
    }
}

extern "C" void kernel_launch(void* const* d_in, const int* in_sizes, int n_in,
                              void* d_out, int out_size) {
    // metadata order: image, cls_pred, reg_pred, anchors
    const float* cls = (const float*)d_in[1];
    const float* reg = (const float*)d_in[2];
    const float* anchors = (const float*)d_in[3];

    int A = in_sizes[3] / 4;                 // 1024
    int B = in_sizes[2] / (4 * A);           // 2
    int C = in_sizes[1] / (B * A);           // 80
    long long hw = (long long)in_sizes[0] / (3LL * B);
    int H = (int)(sqrt((double)hw) + 0.5);   // 2048 (image used for shape only)
    float Hf = (float)H, Wf = (float)H;

    int nBlocks = B * C;                     // 160 blocks, all co-resident (2/SM)
    fused_kernel<<<nBlocks, 1024>>>(cls, reg, anchors, (float*)d_out,
                                    A, C, nBlocks, Wf, Hf);
}